// round 1
// baseline (speedup 1.0000x reference)
#include <cuda_runtime.h>
#include <cstdint>

#define NS 21            // N_STIM + 1
#define PAIRS (NS * NS)  // 441

__global__ void __launch_bounds__(256)
rank_rt_kernel(const int*   __restrict__ stim,    // [B,5]
               const float* __restrict__ table,   // [21,3]
               const float* __restrict__ w,       // [3]
               const float* __restrict__ p_rho,
               const float* __restrict__ p_beta,
               const float* __restrict__ p_tau,
               const float* __restrict__ p_gamma,
               const float* __restrict__ p_upper,
               const float* __restrict__ p_mid,
               const float* __restrict__ p_rate,
               float* __restrict__ out,           // [B*4 rank | B rt]
               int B)
{
    __shared__ float2 sTab[PAIRS];   // {s, s*ln(s)} per (q,r) pair

    // ---- scalars (device-resident; read directly, L2-broadcast) ----
    const float rho   = *p_rho;
    const float beta  = *p_beta;
    const float tau   = *p_tau;
    const float gamma = *p_gamma;
    const float upper = *p_upper;
    const float mid   = *p_mid;
    const float rate  = *p_rate;
    const float inv_rho = 1.0f / rho;
    const float w0 = w[0], w1 = w[1], w2 = w[2];

    // ---- per-block precompute of all 441 pair similarities ----
    for (int e = threadIdx.x; e < PAIRS; e += blockDim.x) {
        const int q = e / NS, r = e % NS;
        const float dx = fabsf(table[q * 3 + 0] - table[r * 3 + 0]);
        const float dy = fabsf(table[q * 3 + 1] - table[r * 3 + 1]);
        const float dz = fabsf(table[q * 3 + 2] - table[r * 3 + 2]);
        const float acc = w0 * powf(dx, rho) + w1 * powf(dy, rho) + w2 * powf(dz, rho);
        const float d   = powf(acc, inv_rho);
        const float s   = expf(-beta * powf(d, tau)) + gamma;
        sTab[e] = make_float2(s, s * logf(s));
    }
    __syncthreads();

    const int nG = B >> 2;                       // full groups of 4 rows
    const int g  = blockIdx.x * blockDim.x + threadIdx.x;
    float* __restrict__ rt_out = out + (size_t)B * 4;

    if (g < nG) {
        // 4 rows = 20 ints = 5 aligned uint4 loads
        const uint4* sp = reinterpret_cast<const uint4*>(stim) + (size_t)g * 5;
        const uint4 v0 = sp[0], v1 = sp[1], v2 = sp[2], v3 = sp[3], v4 = sp[4];
        int idx[20];
        idx[0]=v0.x;  idx[1]=v0.y;  idx[2]=v0.z;  idx[3]=v0.w;
        idx[4]=v1.x;  idx[5]=v1.y;  idx[6]=v1.z;  idx[7]=v1.w;
        idx[8]=v2.x;  idx[9]=v2.y;  idx[10]=v2.z; idx[11]=v2.w;
        idx[12]=v3.x; idx[13]=v3.y; idx[14]=v3.z; idx[15]=v3.w;
        idx[16]=v4.x; idx[17]=v4.y; idx[18]=v4.z; idx[19]=v4.w;

        float4 rt4;
        float* rt4p = &rt4.x;

        #pragma unroll
        for (int rrow = 0; rrow < 4; rrow++) {
            const int base = rrow * 5;
            const int q = idx[base];
            float s0, s1, s2, s3, S, SL;
            {
                const float2 e0 = sTab[q * NS + idx[base + 1]];
                const float2 e1 = sTab[q * NS + idx[base + 2]];
                const float2 e2 = sTab[q * NS + idx[base + 3]];
                const float2 e3 = sTab[q * NS + idx[base + 4]];
                s0 = e0.x; s1 = e1.x; s2 = e2.x; s3 = e3.x;
                S  = (e0.x + e1.x) + (e2.x + e3.x);
                SL = (e0.y + e1.y) + (e2.y + e3.y);
            }
            const float inv = __fdividef(1.0f, S);
            reinterpret_cast<float4*>(out)[(size_t)g * 4 + rrow] =
                make_float4(s0 * inv, s1 * inv, s2 * inv, s3 * inv);

            const float H = __logf(S) - SL * inv;                 // entropy
            rt4p[rrow] = upper * __fdividef(1.0f, 1.0f + __expf(-rate * (H - mid)));
        }
        reinterpret_cast<float4*>(rt_out)[g] = rt4;   // offset 4B+4g is 16B-aligned
    }

    // ---- tail rows (B not divisible by 4) ----
    const int tailN = B & 3;
    if (g < tailN) {
        const int row = (nG << 2) + g;
        const int* rp = stim + (size_t)row * 5;
        const int q = rp[0];
        float s[4], S = 0.0f, SL = 0.0f;
        #pragma unroll
        for (int j = 0; j < 4; j++) {
            const float2 e = sTab[q * NS + rp[1 + j]];
            s[j] = e.x; S += e.x; SL += e.y;
        }
        const float inv = __fdividef(1.0f, S);
        #pragma unroll
        for (int j = 0; j < 4; j++) out[(size_t)row * 4 + j] = s[j] * inv;
        const float H = __logf(S) - SL * inv;
        rt_out[row] = upper * __fdividef(1.0f, 1.0f + __expf(-rate * (H - mid)));
    }
}

extern "C" void kernel_launch(void* const* d_in, const int* in_sizes, int n_in,
                              void* d_out, int out_size)
{
    const int*   stim    = (const int*)  d_in[0];
    const float* table   = (const float*)d_in[1];
    const float* w       = (const float*)d_in[2];
    const float* p_rho   = (const float*)d_in[3];
    const float* p_beta  = (const float*)d_in[4];
    const float* p_tau   = (const float*)d_in[5];
    const float* p_gamma = (const float*)d_in[6];
    const float* p_upper = (const float*)d_in[7];
    const float* p_mid   = (const float*)d_in[8];
    const float* p_rate  = (const float*)d_in[9];

    const int B  = in_sizes[0] / 5;
    const int nG = B >> 2;
    const int threads = 256;
    int blocks = (nG + threads - 1) / threads;
    if (blocks < 1) blocks = 1;

    rank_rt_kernel<<<blocks, threads>>>(stim, table, w,
                                        p_rho, p_beta, p_tau, p_gamma,
                                        p_upper, p_mid, p_rate,
                                        (float*)d_out, B);
}

// round 2
// speedup vs baseline: 1.1327x; 1.1327x over previous
#include <cuda_runtime.h>
#include <cstdint>

#define NS 21            // N_STIM + 1
#define PAIRS (NS * NS)  // 441

__device__ float2 g_tab[PAIRS];   // {s, s*ln(s)} per (q,r) pair

// ---------------- kernel 1: one block computes the 441-entry pair table ----------------
__global__ void precompute_kernel(const float* __restrict__ table,
                                  const float* __restrict__ w,
                                  const float* __restrict__ p_rho,
                                  const float* __restrict__ p_beta,
                                  const float* __restrict__ p_tau,
                                  const float* __restrict__ p_gamma)
{
    const int e = blockIdx.x * blockDim.x + threadIdx.x;
    if (e >= PAIRS) return;
    const float rho   = *p_rho;
    const float beta  = *p_beta;
    const float tau   = *p_tau;
    const float gamma = *p_gamma;
    const float inv_rho = 1.0f / rho;
    const float w0 = w[0], w1 = w[1], w2 = w[2];

    const int q = e / NS, r = e % NS;
    const float dx = fabsf(table[q * 3 + 0] - table[r * 3 + 0]);
    const float dy = fabsf(table[q * 3 + 1] - table[r * 3 + 1]);
    const float dz = fabsf(table[q * 3 + 2] - table[r * 3 + 2]);
    const float acc = w0 * powf(dx, rho) + w1 * powf(dy, rho) + w2 * powf(dz, rho);
    const float d   = powf(acc, inv_rho);
    const float s   = expf(-beta * powf(d, tau)) + gamma;
    g_tab[e] = make_float2(s, s * logf(s));
}

// ---------------- kernel 2: main lookup kernel ----------------
__global__ void __launch_bounds__(256)
rank_rt_kernel(const int*   __restrict__ stim,    // [B,5]
               const float* __restrict__ p_upper,
               const float* __restrict__ p_mid,
               const float* __restrict__ p_rate,
               float* __restrict__ out,           // [B*4 rank | B rt]
               int B)
{
    __shared__ float2 sTab[PAIRS];

    // cheap copy: 441 float2 from global table (computed once by kernel 1)
    for (int e = threadIdx.x; e < PAIRS; e += blockDim.x)
        sTab[e] = g_tab[e];
    __syncthreads();

    const float upper = *p_upper;
    const float mid   = *p_mid;
    const float rate  = *p_rate;

    const int nG = B >> 2;                       // full groups of 4 rows
    const int g  = blockIdx.x * blockDim.x + threadIdx.x;
    float* __restrict__ rt_out = out + (size_t)B * 4;

    if (g < nG) {
        // 4 rows = 20 ints = 5 aligned uint4 loads
        const uint4* sp = reinterpret_cast<const uint4*>(stim) + (size_t)g * 5;
        const uint4 v0 = sp[0], v1 = sp[1], v2 = sp[2], v3 = sp[3], v4 = sp[4];
        int idx[20];
        idx[0]=v0.x;  idx[1]=v0.y;  idx[2]=v0.z;  idx[3]=v0.w;
        idx[4]=v1.x;  idx[5]=v1.y;  idx[6]=v1.z;  idx[7]=v1.w;
        idx[8]=v2.x;  idx[9]=v2.y;  idx[10]=v2.z; idx[11]=v2.w;
        idx[12]=v3.x; idx[13]=v3.y; idx[14]=v3.z; idx[15]=v3.w;
        idx[16]=v4.x; idx[17]=v4.y; idx[18]=v4.z; idx[19]=v4.w;

        float4 rt4;
        float* rt4p = &rt4.x;

        #pragma unroll
        for (int rrow = 0; rrow < 4; rrow++) {
            const int base = rrow * 5;
            const int qb = idx[base] * NS;
            const float2 e0 = sTab[qb + idx[base + 1]];
            const float2 e1 = sTab[qb + idx[base + 2]];
            const float2 e2 = sTab[qb + idx[base + 3]];
            const float2 e3 = sTab[qb + idx[base + 4]];
            const float S  = (e0.x + e1.x) + (e2.x + e3.x);
            const float SL = (e0.y + e1.y) + (e2.y + e3.y);

            const float inv = __fdividef(1.0f, S);
            reinterpret_cast<float4*>(out)[(size_t)g * 4 + rrow] =
                make_float4(e0.x * inv, e1.x * inv, e2.x * inv, e3.x * inv);

            const float H = __logf(S) - SL * inv;                 // entropy
            rt4p[rrow] = upper * __fdividef(1.0f, 1.0f + __expf(-rate * (H - mid)));
        }
        reinterpret_cast<float4*>(rt_out)[g] = rt4;   // offset 4B+4g is 16B-aligned
    }

    // ---- tail rows (B not divisible by 4) ----
    const int tailN = B & 3;
    if (g < tailN) {
        const int row = (nG << 2) + g;
        const int* rp = stim + (size_t)row * 5;
        const int qb = rp[0] * NS;
        float s[4], S = 0.0f, SL = 0.0f;
        #pragma unroll
        for (int j = 0; j < 4; j++) {
            const float2 e = sTab[qb + rp[1 + j]];
            s[j] = e.x; S += e.x; SL += e.y;
        }
        const float inv = __fdividef(1.0f, S);
        #pragma unroll
        for (int j = 0; j < 4; j++) out[(size_t)row * 4 + j] = s[j] * inv;
        const float H = __logf(S) - SL * inv;
        rt_out[row] = upper * __fdividef(1.0f, 1.0f + __expf(-rate * (H - mid)));
    }
}

extern "C" void kernel_launch(void* const* d_in, const int* in_sizes, int n_in,
                              void* d_out, int out_size)
{
    const int*   stim    = (const int*)  d_in[0];
    const float* table   = (const float*)d_in[1];
    const float* w       = (const float*)d_in[2];
    const float* p_rho   = (const float*)d_in[3];
    const float* p_beta  = (const float*)d_in[4];
    const float* p_tau   = (const float*)d_in[5];
    const float* p_gamma = (const float*)d_in[6];
    const float* p_upper = (const float*)d_in[7];
    const float* p_mid   = (const float*)d_in[8];
    const float* p_rate  = (const float*)d_in[9];

    const int B  = in_sizes[0] / 5;
    const int nG = B >> 2;
    const int threads = 256;
    int blocks = (nG + threads - 1) / threads;
    if (blocks < 1) blocks = 1;

    precompute_kernel<<<1, 512>>>(table, w, p_rho, p_beta, p_tau, p_gamma);
    rank_rt_kernel<<<blocks, threads>>>(stim, p_upper, p_mid, p_rate,
                                        (float*)d_out, B);
}

// round 4
// speedup vs baseline: 1.2709x; 1.1220x over previous
#include <cuda_runtime.h>
#include <cstdint>

#define NS 21            // N_STIM + 1
#define PAIRS (NS * NS)  // 441
#define TPB 256

__device__ float2 g_tab[PAIRS];   // {s, s*ln(s)} per (q,r) pair

// ---------------- kernel 1: one small grid computes the 441-entry pair table ----------------
__global__ void precompute_kernel(const float* __restrict__ table,
                                  const float* __restrict__ w,
                                  const float* __restrict__ p_rho,
                                  const float* __restrict__ p_beta,
                                  const float* __restrict__ p_tau,
                                  const float* __restrict__ p_gamma)
{
    const int e = blockIdx.x * blockDim.x + threadIdx.x;
    if (e >= PAIRS) return;
    const float rho   = *p_rho;
    const float beta  = *p_beta;
    const float tau   = *p_tau;
    const float gamma = *p_gamma;
    const float inv_rho = 1.0f / rho;
    const float w0 = w[0], w1 = w[1], w2 = w[2];

    const int q = e / NS, r = e % NS;
    const float dx = fabsf(table[q * 3 + 0] - table[r * 3 + 0]);
    const float dy = fabsf(table[q * 3 + 1] - table[r * 3 + 1]);
    const float dz = fabsf(table[q * 3 + 2] - table[r * 3 + 2]);
    const float acc = w0 * powf(dx, rho) + w1 * powf(dy, rho) + w2 * powf(dz, rho);
    const float d   = powf(acc, inv_rho);
    const float s   = expf(-beta * powf(d, tau)) + gamma;
    g_tab[e] = make_float2(s, s * logf(s));
}

// ---------------- kernel 2: main lookup kernel, fully coalesced ----------------
__global__ void __launch_bounds__(TPB)
rank_rt_kernel(const int*   __restrict__ stim,    // [B,5]
               const float* __restrict__ p_upper,
               const float* __restrict__ p_mid,
               const float* __restrict__ p_rate,
               float* __restrict__ out,           // [B*4 rank | B rt]
               int B)
{
    __shared__ float2 sTab[PAIRS];
    __shared__ int    sIdx[TPB * 5];

    // table copy (cheap: ~2 LDG/STS per thread, g_tab lives in L2)
    for (int e = threadIdx.x; e < PAIRS; e += TPB)
        sTab[e] = g_tab[e];

    // coalesced staging of this block's 256 rows of indices (5 LDG.32, unit stride)
    const int row0  = blockIdx.x * TPB;
    const int gbase = row0 * 5;
    const int total = B * 5;
    #pragma unroll
    for (int i = 0; i < 5; i++) {
        const int off  = threadIdx.x + i * TPB;
        const int gidx = gbase + off;
        sIdx[off] = (gidx < total) ? stim[gidx] : 0;
    }
    __syncthreads();

    const int row = row0 + threadIdx.x;
    if (row >= B) return;

    const float upper = *p_upper;
    const float mid   = *p_mid;
    const float rate  = *p_rate;

    // stride-5 shared read: 5 is odd -> bank-conflict-free
    const int* rp = &sIdx[threadIdx.x * 5];
    const int qb = rp[0] * NS;
    const float2 e0 = sTab[qb + rp[1]];
    const float2 e1 = sTab[qb + rp[2]];
    const float2 e2 = sTab[qb + rp[3]];
    const float2 e3 = sTab[qb + rp[4]];

    const float S  = (e0.x + e1.x) + (e2.x + e3.x);
    const float SL = (e0.y + e1.y) + (e2.y + e3.y);
    const float inv = __fdividef(1.0f, S);

    // coalesced STG.128: lane stride is exactly 16B
    reinterpret_cast<float4*>(out)[row] =
        make_float4(e0.x * inv, e1.x * inv, e2.x * inv, e3.x * inv);

    const float H = __logf(S) - SL * inv;         // entropy
    // coalesced STG.32
    out[(size_t)B * 4 + row] =
        upper * __fdividef(1.0f, 1.0f + __expf(-rate * (H - mid)));
}

extern "C" void kernel_launch(void* const* d_in, const int* in_sizes, int n_in,
                              void* d_out, int out_size)
{
    const int*   stim    = (const int*)  d_in[0];
    const float* table   = (const float*)d_in[1];
    const float* w       = (const float*)d_in[2];
    const float* p_rho   = (const float*)d_in[3];
    const float* p_beta  = (const float*)d_in[4];
    const float* p_tau   = (const float*)d_in[5];
    const float* p_gamma = (const float*)d_in[6];
    const float* p_upper = (const float*)d_in[7];
    const float* p_mid   = (const float*)d_in[8];
    const float* p_rate  = (const float*)d_in[9];

    const int B = in_sizes[0] / 5;
    int blocks = (B + TPB - 1) / TPB;
    if (blocks < 1) blocks = 1;

    precompute_kernel<<<1, 512>>>(table, w, p_rho, p_beta, p_tau, p_gamma);
    rank_rt_kernel<<<blocks, TPB>>>(stim, p_upper, p_mid, p_rate,
                                    (float*)d_out, B);
}

// round 6
// speedup vs baseline: 1.3659x; 1.0747x over previous
#include <cuda_runtime.h>
#include <cstdint>

#define NS 21            // N_STIM + 1
#define PAIRS (NS * NS)  // 441
#define TPB 256
#define RPB (TPB * 2)    // 512 rows per block
#define NU4 (RPB * 5 / 4)// 640 uint4 of indices per block

__device__ float2 g_tab[PAIRS];   // {s, s*ln(s)} per (q,r) pair

// ---------------- kernel 1: compute the 441-entry pair table once ----------------
__global__ void precompute_kernel(const float* __restrict__ table,
                                  const float* __restrict__ w,
                                  const float* __restrict__ p_rho,
                                  const float* __restrict__ p_beta,
                                  const float* __restrict__ p_tau,
                                  const float* __restrict__ p_gamma)
{
    const int e = blockIdx.x * blockDim.x + threadIdx.x;
    if (e >= PAIRS) return;
    const float rho   = *p_rho;
    const float beta  = *p_beta;
    const float tau   = *p_tau;
    const float gamma = *p_gamma;
    const float inv_rho = 1.0f / rho;
    const float w0 = w[0], w1 = w[1], w2 = w[2];

    const int q = e / NS, r = e % NS;
    const float dx = fabsf(table[q * 3 + 0] - table[r * 3 + 0]);
    const float dy = fabsf(table[q * 3 + 1] - table[r * 3 + 1]);
    const float dz = fabsf(table[q * 3 + 2] - table[r * 3 + 2]);
    const float acc = w0 * powf(dx, rho) + w1 * powf(dy, rho) + w2 * powf(dz, rho);
    const float d   = powf(acc, inv_rho);
    const float s   = expf(-beta * powf(d, tau)) + gamma;
    g_tab[e] = make_float2(s, s * logf(s));
}

// ---------------- kernel 2: main lookup kernel, 2 rows/thread ----------------
__global__ void __launch_bounds__(TPB)
rank_rt_kernel(const int*   __restrict__ stim,    // [B,5]
               const float* __restrict__ p_upper,
               const float* __restrict__ p_mid,
               const float* __restrict__ p_rate,
               float* __restrict__ out,           // [B*4 rank | B rt]
               int B)
{
    __shared__ float2 sTab[PAIRS];
    __shared__ uint4  sIdxV[NU4];
    int* sIdx = reinterpret_cast<int*>(sIdxV);

    // table copy (441 float2 via L2-resident global)
    for (int e = threadIdx.x; e < PAIRS; e += TPB)
        sTab[e] = g_tab[e];

    // coalesced vectorized staging: 640 uint4 per block (2.5 per thread)
    const int row0 = blockIdx.x * RPB;
    {
        const uint4* gsp = reinterpret_cast<const uint4*>(stim);
        const long baseU4  = (long)row0 * 5 / 4;          // row0*5 divisible by 4
        const long totalU4 = (long)B * 5 / 4;             // B*5 divisible by 4 when B%4==0
        const long totalI  = (long)B * 5;
        #pragma unroll
        for (int i = 0; i < 3; i++) {
            const int off = threadIdx.x + i * TPB;
            if (off < NU4) {
                const long gu = baseU4 + off;
                if (gu + 1 <= totalU4) {
                    sIdxV[off] = gsp[gu];
                } else {
                    // scalar tail (only last partial block, only if B*5 % 4 != 0)
                    uint4 v = make_uint4(0, 0, 0, 0);
                    const long gi = gu * 4;
                    unsigned* vp = &v.x;
                    #pragma unroll
                    for (int c = 0; c < 4; c++)
                        if (gi + c < totalI) vp[c] = (unsigned)stim[gi + c];
                    sIdxV[off] = v;
                }
            }
        }
    }
    __syncthreads();

    const float upper = *p_upper;
    const float mid   = *p_mid;
    const float rate  = *p_rate;
    float* __restrict__ rt_out = out + (size_t)B * 4;

    // two independent rows per thread: r_a = row0+tid, r_b = row0+TPB+tid
    #pragma unroll
    for (int h = 0; h < 2; h++) {
        const int lrow = threadIdx.x + h * TPB;     // local row in block
        const int row  = row0 + lrow;
        if (row >= B) break;

        const int* rp = &sIdx[lrow * 5];            // stride-5: bank-conflict-free
        const int qb = rp[0] * NS;
        const float2 e0 = sTab[qb + rp[1]];
        const float2 e1 = sTab[qb + rp[2]];
        const float2 e2 = sTab[qb + rp[3]];
        const float2 e3 = sTab[qb + rp[4]];

        const float S  = (e0.x + e1.x) + (e2.x + e3.x);
        const float SL = (e0.y + e1.y) + (e2.y + e3.y);
        const float inv = __fdividef(1.0f, S);

        // coalesced STG.128 (lane stride 16B)
        reinterpret_cast<float4*>(out)[row] =
            make_float4(e0.x * inv, e1.x * inv, e2.x * inv, e3.x * inv);

        const float H = __logf(S) - SL * inv;       // entropy
        rt_out[row] = upper * __fdividef(1.0f, 1.0f + __expf(-rate * (H - mid)));
    }
}

extern "C" void kernel_launch(void* const* d_in, const int* in_sizes, int n_in,
                              void* d_out, int out_size)
{
    const int*   stim    = (const int*)  d_in[0];
    const float* table   = (const float*)d_in[1];
    const float* w       = (const float*)d_in[2];
    const float* p_rho   = (const float*)d_in[3];
    const float* p_beta  = (const float*)d_in[4];
    const float* p_tau   = (const float*)d_in[5];
    const float* p_gamma = (const float*)d_in[6];
    const float* p_upper = (const float*)d_in[7];
    const float* p_mid   = (const float*)d_in[8];
    const float* p_rate  = (const float*)d_in[9];

    const int B = in_sizes[0] / 5;
    int blocks = (B + RPB - 1) / RPB;
    if (blocks < 1) blocks = 1;

    precompute_kernel<<<1, 512>>>(table, w, p_rho, p_beta, p_tau, p_gamma);
    rank_rt_kernel<<<blocks, TPB>>>(stim, p_upper, p_mid, p_rate,
                                    (float*)d_out, B);
}

// round 7
// speedup vs baseline: 1.3978x; 1.0234x over previous
#include <cuda_runtime.h>
#include <cstdint>

#define NS 21            // N_STIM + 1
#define PAIRS (NS * NS)  // 441
#define TPB 256
#define RPB (TPB * 4)    // 1024 rows per block
#define NU4 (RPB * 5 / 4)// 1280 uint4 of indices per block

__device__ float2 g_tab[PAIRS];   // {s, s*ln(s)} per (q,r) pair

// ---------------- kernel 1: compute the 441-entry pair table once ----------------
__global__ void precompute_kernel(const float* __restrict__ table,
                                  const float* __restrict__ w,
                                  const float* __restrict__ p_rho,
                                  const float* __restrict__ p_beta,
                                  const float* __restrict__ p_tau,
                                  const float* __restrict__ p_gamma)
{
    const int e = blockIdx.x * blockDim.x + threadIdx.x;
    if (e >= PAIRS) return;
    const float rho   = *p_rho;
    const float beta  = *p_beta;
    const float tau   = *p_tau;
    const float gamma = *p_gamma;
    const float inv_rho = 1.0f / rho;
    const float w0 = w[0], w1 = w[1], w2 = w[2];

    const int q = e / NS, r = e % NS;
    const float dx = fabsf(table[q * 3 + 0] - table[r * 3 + 0]);
    const float dy = fabsf(table[q * 3 + 1] - table[r * 3 + 1]);
    const float dz = fabsf(table[q * 3 + 2] - table[r * 3 + 2]);
    const float acc = w0 * powf(dx, rho) + w1 * powf(dy, rho) + w2 * powf(dz, rho);
    const float d   = powf(acc, inv_rho);
    const float s   = expf(-beta * powf(d, tau)) + gamma;
    g_tab[e] = make_float2(s, s * logf(s));
}

// ---------------- kernel 2: main lookup kernel, 4 rows/thread, prefetch overlap ----------------
__global__ void __launch_bounds__(TPB)
rank_rt_kernel(const int*   __restrict__ stim,    // [B,5]
               const float* __restrict__ p_upper,
               const float* __restrict__ p_mid,
               const float* __restrict__ p_rate,
               float* __restrict__ out,           // [B*4 rank | B rt]
               int B)
{
    __shared__ float2 sTab[PAIRS];
    __shared__ uint4  sIdxV[NU4];
    int* sIdx = reinterpret_cast<int*>(sIdxV);

    const int row0 = blockIdx.x * RPB;

    // ---- 1) prefetch this block's index data into registers (LDGs issued first) ----
    uint4 pf[5];
    {
        const uint4* gsp = reinterpret_cast<const uint4*>(stim);
        const long baseU4  = (long)row0 * 5 / 4;   // row0*5 divisible by 4 (RPB%4==0)
        const long totalU4 = ((long)B * 5) / 4;
        const long totalI  = (long)B * 5;
        #pragma unroll
        for (int i = 0; i < 5; i++) {
            const long gu = baseU4 + threadIdx.x + i * TPB;
            if (gu < totalU4) {
                pf[i] = gsp[gu];
            } else {
                uint4 v = make_uint4(0, 0, 0, 0);
                const long gi = gu * 4;
                unsigned* vp = &v.x;
                #pragma unroll
                for (int c = 0; c < 4; c++)
                    if (gi + c < totalI) vp[c] = (unsigned)stim[gi + c];
                pf[i] = v;
            }
        }
    }

    // ---- 2) table copy overlaps the prefetch latency ----
    for (int e = threadIdx.x; e < PAIRS; e += TPB)
        sTab[e] = g_tab[e];

    // ---- 3) store prefetched indices to shared; single barrier ----
    #pragma unroll
    for (int i = 0; i < 5; i++)
        sIdxV[threadIdx.x + i * TPB] = pf[i];
    __syncthreads();

    const float upper = *p_upper;
    const float mid   = *p_mid;
    const float rate  = *p_rate;
    float* __restrict__ rt_out = out + (size_t)B * 4;

    // ---- 4) four independent rows per thread ----
    #pragma unroll
    for (int h = 0; h < 4; h++) {
        const int lrow = threadIdx.x + h * TPB;
        const int row  = row0 + lrow;
        if (row >= B) break;

        const int* rp = &sIdx[lrow * 5];            // stride-5: bank-conflict-free
        const int qb = rp[0] * NS;
        const float2 e0 = sTab[qb + rp[1]];
        const float2 e1 = sTab[qb + rp[2]];
        const float2 e2 = sTab[qb + rp[3]];
        const float2 e3 = sTab[qb + rp[4]];

        const float S  = (e0.x + e1.x) + (e2.x + e3.x);
        const float SL = (e0.y + e1.y) + (e2.y + e3.y);
        const float inv = __fdividef(1.0f, S);

        // coalesced STG.128 (lane stride 16B)
        reinterpret_cast<float4*>(out)[row] =
            make_float4(e0.x * inv, e1.x * inv, e2.x * inv, e3.x * inv);

        const float H = __logf(S) - SL * inv;       // entropy
        rt_out[row] = upper * __fdividef(1.0f, 1.0f + __expf(-rate * (H - mid)));
    }
}

extern "C" void kernel_launch(void* const* d_in, const int* in_sizes, int n_in,
                              void* d_out, int out_size)
{
    const int*   stim    = (const int*)  d_in[0];
    const float* table   = (const float*)d_in[1];
    const float* w       = (const float*)d_in[2];
    const float* p_rho   = (const float*)d_in[3];
    const float* p_beta  = (const float*)d_in[4];
    const float* p_tau   = (const float*)d_in[5];
    const float* p_gamma = (const float*)d_in[6];
    const float* p_upper = (const float*)d_in[7];
    const float* p_mid   = (const float*)d_in[8];
    const float* p_rate  = (const float*)d_in[9];

    const int B = in_sizes[0] / 5;
    int blocks = (B + RPB - 1) / RPB;
    if (blocks < 1) blocks = 1;

    precompute_kernel<<<1, 512>>>(table, w, p_rho, p_beta, p_tau, p_gamma);
    rank_rt_kernel<<<blocks, TPB>>>(stim, p_upper, p_mid, p_rate,
                                    (float*)d_out, B);
}

// round 8
// speedup vs baseline: 1.4810x; 1.0595x over previous
#include <cuda_runtime.h>
#include <cstdint>

#define NS 21             // N_STIM + 1
#define PAIRS (NS * NS)   // 441
#define TPB 256
#define RPT 8             // rows per thread
#define RPB (TPB * RPT)   // 2048 rows per block
#define NU4 (RPB * 5 / 4) // 2560 uint4 of indices per block

__device__ float2 g_tab[PAIRS];   // {s, s*ln(s)} per (q,r) pair

// ---------------- kernel 1: compute the 441-entry pair table once ----------------
__global__ void precompute_kernel(const float* __restrict__ table,
                                  const float* __restrict__ w,
                                  const float* __restrict__ p_rho,
                                  const float* __restrict__ p_beta,
                                  const float* __restrict__ p_tau,
                                  const float* __restrict__ p_gamma)
{
    const int e = blockIdx.x * blockDim.x + threadIdx.x;
    if (e >= PAIRS) return;
    const float rho   = *p_rho;
    const float beta  = *p_beta;
    const float tau   = *p_tau;
    const float gamma = *p_gamma;
    const float w0 = w[0], w1 = w[1], w2 = w[2];

    const int q = e / NS, r = e % NS;
    const float dx = fabsf(table[q * 3 + 0] - table[r * 3 + 0]);
    const float dy = fabsf(table[q * 3 + 1] - table[r * 3 + 1]);
    const float dz = fabsf(table[q * 3 + 2] - table[r * 3 + 2]);

    float s;
    if (rho == 2.0f && tau == 1.0f) {
        // fast path (matches the actual parameterization): no powf at all
        const float acc = w0 * dx * dx + w1 * dy * dy + w2 * dz * dz;
        const float d   = sqrtf(acc);
        s = __expf(-beta * d) + gamma;
    } else {
        const float inv_rho = 1.0f / rho;
        const float acc = w0 * powf(dx, rho) + w1 * powf(dy, rho) + w2 * powf(dz, rho);
        const float d   = powf(acc, inv_rho);
        s = expf(-beta * powf(d, tau)) + gamma;
    }
    g_tab[e] = make_float2(s, s * __logf(s));
}

// ---------------- kernel 2: main lookup kernel, 8 rows/thread ----------------
__global__ void __launch_bounds__(TPB)
rank_rt_kernel(const int*   __restrict__ stim,    // [B,5]
               const float* __restrict__ p_upper,
               const float* __restrict__ p_mid,
               const float* __restrict__ p_rate,
               float* __restrict__ out,           // [B*4 rank | B rt]
               int B)
{
    __shared__ float2 sTab[PAIRS];
    __shared__ uint4  sIdxV[NU4];
    int* sIdx = reinterpret_cast<int*>(sIdxV);

    const int row0 = blockIdx.x * RPB;
    const uint4* gsp = reinterpret_cast<const uint4*>(stim);
    const long baseU4  = (long)row0 * 5 / 4;       // row0*5 divisible by 4 (RPB%4==0)
    const long totalU4 = ((long)B * 5) / 4;
    const long totalI  = (long)B * 5;

    // ---- wave A: prefetch first 5 uint4 into regs (LDGs in flight) ----
    uint4 pf[5];
    #pragma unroll
    for (int i = 0; i < 5; i++) {
        const long gu = baseU4 + threadIdx.x + i * TPB;
        if (gu < totalU4) {
            pf[i] = gsp[gu];
        } else {
            uint4 v = make_uint4(0, 0, 0, 0);
            const long gi = gu * 4;
            unsigned* vp = &v.x;
            #pragma unroll
            for (int c = 0; c < 4; c++)
                if (gi + c < totalI) vp[c] = (unsigned)stim[gi + c];
            pf[i] = v;
        }
    }

    // ---- table copy overlaps wave-A latency ----
    for (int e = threadIdx.x; e < PAIRS; e += TPB)
        sTab[e] = g_tab[e];

    // ---- drain wave A, issue wave B ----
    #pragma unroll
    for (int i = 0; i < 5; i++)
        sIdxV[threadIdx.x + i * TPB] = pf[i];

    #pragma unroll
    for (int i = 0; i < 5; i++) {
        const long gu = baseU4 + threadIdx.x + (i + 5) * TPB;
        if (gu < totalU4) {
            pf[i] = gsp[gu];
        } else {
            uint4 v = make_uint4(0, 0, 0, 0);
            const long gi = gu * 4;
            unsigned* vp = &v.x;
            #pragma unroll
            for (int c = 0; c < 4; c++)
                if (gi + c < totalI) vp[c] = (unsigned)stim[gi + c];
            pf[i] = v;
        }
    }
    #pragma unroll
    for (int i = 0; i < 5; i++)
        sIdxV[threadIdx.x + (i + 5) * TPB] = pf[i];

    __syncthreads();

    const float upper = *p_upper;
    const float mid   = *p_mid;
    const float rate  = *p_rate;
    float* __restrict__ rt_out = out + (size_t)B * 4;

    // ---- eight independent rows per thread ----
    #pragma unroll
    for (int h = 0; h < RPT; h++) {
        const int lrow = threadIdx.x + h * TPB;
        const int row  = row0 + lrow;
        if (row >= B) break;

        const int* rp = &sIdx[lrow * 5];            // stride-5: bank-conflict-free
        const int qb = rp[0] * NS;
        const float2 e0 = sTab[qb + rp[1]];
        const float2 e1 = sTab[qb + rp[2]];
        const float2 e2 = sTab[qb + rp[3]];
        const float2 e3 = sTab[qb + rp[4]];

        const float S  = (e0.x + e1.x) + (e2.x + e3.x);
        const float SL = (e0.y + e1.y) + (e2.y + e3.y);
        const float inv = __fdividef(1.0f, S);

        // coalesced STG.128 (lane stride 16B)
        reinterpret_cast<float4*>(out)[row] =
            make_float4(e0.x * inv, e1.x * inv, e2.x * inv, e3.x * inv);

        const float H = __logf(S) - SL * inv;       // entropy
        rt_out[row] = upper * __fdividef(1.0f, 1.0f + __expf(-rate * (H - mid)));
    }
}

extern "C" void kernel_launch(void* const* d_in, const int* in_sizes, int n_in,
                              void* d_out, int out_size)
{
    const int*   stim    = (const int*)  d_in[0];
    const float* table   = (const float*)d_in[1];
    const float* w       = (const float*)d_in[2];
    const float* p_rho   = (const float*)d_in[3];
    const float* p_beta  = (const float*)d_in[4];
    const float* p_tau   = (const float*)d_in[5];
    const float* p_gamma = (const float*)d_in[6];
    const float* p_upper = (const float*)d_in[7];
    const float* p_mid   = (const float*)d_in[8];
    const float* p_rate  = (const float*)d_in[9];

    const int B = in_sizes[0] / 5;
    int blocks = (B + RPB - 1) / RPB;
    if (blocks < 1) blocks = 1;

    precompute_kernel<<<2, 256>>>(table, w, p_rho, p_beta, p_tau, p_gamma);
    rank_rt_kernel<<<blocks, TPB>>>(stim, p_upper, p_mid, p_rate,
                                    (float*)d_out, B);
}

// round 9
// speedup vs baseline: 1.5290x; 1.0324x over previous
#include <cuda_runtime.h>
#include <cstdint>

#define NS 21             // N_STIM + 1
#define PAIRS (NS * NS)   // 441
#define TPB 256
#define RPT 4             // rows per thread
#define RPB (TPB * RPT)   // 1024 rows per block
#define NU4 (RPB * 5 / 4) // 1280 uint4 of indices per block (5 per thread)

__device__ float2 g_tab[PAIRS];   // {s, s*ln(s)} per (q,r) pair

// ---------------- kernel 1: compute the 441-entry pair table once ----------------
__global__ void precompute_kernel(const float* __restrict__ table,
                                  const float* __restrict__ w,
                                  const float* __restrict__ p_rho,
                                  const float* __restrict__ p_beta,
                                  const float* __restrict__ p_tau,
                                  const float* __restrict__ p_gamma)
{
    const int e = blockIdx.x * blockDim.x + threadIdx.x;
    if (e >= PAIRS) return;
    const float rho   = *p_rho;
    const float beta  = *p_beta;
    const float tau   = *p_tau;
    const float gamma = *p_gamma;
    const float w0 = w[0], w1 = w[1], w2 = w[2];

    const int q = e / NS, r = e % NS;
    const float dx = fabsf(table[q * 3 + 0] - table[r * 3 + 0]);
    const float dy = fabsf(table[q * 3 + 1] - table[r * 3 + 1]);
    const float dz = fabsf(table[q * 3 + 2] - table[r * 3 + 2]);

    float s;
    if (rho == 2.0f && tau == 1.0f) {
        // fast path for the actual parameterization: no powf
        const float acc = w0 * dx * dx + w1 * dy * dy + w2 * dz * dz;
        const float d   = sqrtf(acc);
        s = __expf(-beta * d) + gamma;
    } else {
        const float inv_rho = 1.0f / rho;
        const float acc = w0 * powf(dx, rho) + w1 * powf(dy, rho) + w2 * powf(dz, rho);
        const float d   = powf(acc, inv_rho);
        s = expf(-beta * powf(d, tau)) + gamma;
    }
    g_tab[e] = make_float2(s, s * __logf(s));
}

// ---------------- kernel 2: main lookup kernel, 4 rows/thread, 2-row pipelined ----------------
__global__ void __launch_bounds__(TPB, 6)
rank_rt_kernel(const int*   __restrict__ stim,    // [B,5]
               const float* __restrict__ p_upper,
               const float* __restrict__ p_mid,
               const float* __restrict__ p_rate,
               float* __restrict__ out,           // [B*4 rank | B rt]
               int B)
{
    __shared__ float2 sTab[PAIRS];
    __shared__ uint4  sIdxV[NU4];
    int* sIdx = reinterpret_cast<int*>(sIdxV);

    const int row0 = blockIdx.x * RPB;
    const uint4* gsp = reinterpret_cast<const uint4*>(stim);
    const long baseU4  = (long)row0 * 5 / 4;       // row0*5 divisible by 4 (RPB%4==0)
    const long totalU4 = ((long)B * 5) / 4;
    const long totalI  = (long)B * 5;

    // ---- 1) prefetch 5 uint4/thread into regs (LDGs issued first) ----
    uint4 pf[5];
    #pragma unroll
    for (int i = 0; i < 5; i++) {
        const long gu = baseU4 + threadIdx.x + i * TPB;
        if (gu < totalU4) {
            pf[i] = gsp[gu];
        } else {
            uint4 v = make_uint4(0, 0, 0, 0);
            const long gi = gu * 4;
            unsigned* vp = &v.x;
            #pragma unroll
            for (int c = 0; c < 4; c++)
                if (gi + c < totalI) vp[c] = (unsigned)stim[gi + c];
            pf[i] = v;
        }
    }

    // ---- 2) table copy overlaps prefetch latency ----
    for (int e = threadIdx.x; e < PAIRS; e += TPB)
        sTab[e] = g_tab[e];

    // ---- 3) drain prefetch to shared; single barrier ----
    #pragma unroll
    for (int i = 0; i < 5; i++)
        sIdxV[threadIdx.x + i * TPB] = pf[i];
    __syncthreads();

    const float upper = *p_upper;
    const float mid   = *p_mid;
    const float rate  = *p_rate;
    float* __restrict__ rt_out = out + (size_t)B * 4;

    // ---- 4) process rows in pairs: batch all loads, then all math ----
    #pragma unroll
    for (int hh = 0; hh < RPT; hh += 2) {
        const int la = threadIdx.x + hh * TPB;
        const int lb = la + TPB;
        const int ra = row0 + la;
        const int rb = row0 + lb;

        // batch 1: both rows' indices (10 independent LDS.32, conflict-free stride-5)
        int ia[5], ib[5];
        #pragma unroll
        for (int c = 0; c < 5; c++) ia[c] = sIdx[la * 5 + c];
        #pragma unroll
        for (int c = 0; c < 5; c++) ib[c] = sIdx[lb * 5 + c];

        // batch 2: all 8 table lookups in flight
        const int qa = ia[0] * NS;
        const int qb = ib[0] * NS;
        float2 ea[4], eb[4];
        #pragma unroll
        for (int c = 0; c < 4; c++) ea[c] = sTab[qa + ia[c + 1]];
        #pragma unroll
        for (int c = 0; c < 4; c++) eb[c] = sTab[qb + ib[c + 1]];

        // batch 3: math + stores
        if (ra < B) {
            const float S  = (ea[0].x + ea[1].x) + (ea[2].x + ea[3].x);
            const float SL = (ea[0].y + ea[1].y) + (ea[2].y + ea[3].y);
            const float inv = __fdividef(1.0f, S);
            reinterpret_cast<float4*>(out)[ra] =
                make_float4(ea[0].x * inv, ea[1].x * inv, ea[2].x * inv, ea[3].x * inv);
            const float H = __logf(S) - SL * inv;
            rt_out[ra] = upper * __fdividef(1.0f, 1.0f + __expf(-rate * (H - mid)));
        }
        if (rb < B) {
            const float S  = (eb[0].x + eb[1].x) + (eb[2].x + eb[3].x);
            const float SL = (eb[0].y + eb[1].y) + (eb[2].y + eb[3].y);
            const float inv = __fdividef(1.0f, S);
            reinterpret_cast<float4*>(out)[rb] =
                make_float4(eb[0].x * inv, eb[1].x * inv, eb[2].x * inv, eb[3].x * inv);
            const float H = __logf(S) - SL * inv;
            rt_out[rb] = upper * __fdividef(1.0f, 1.0f + __expf(-rate * (H - mid)));
        }
    }
}

extern "C" void kernel_launch(void* const* d_in, const int* in_sizes, int n_in,
                              void* d_out, int out_size)
{
    const int*   stim    = (const int*)  d_in[0];
    const float* table   = (const float*)d_in[1];
    const float* w       = (const float*)d_in[2];
    const float* p_rho   = (const float*)d_in[3];
    const float* p_beta  = (const float*)d_in[4];
    const float* p_tau   = (const float*)d_in[5];
    const float* p_gamma = (const float*)d_in[6];
    const float* p_upper = (const float*)d_in[7];
    const float* p_mid   = (const float*)d_in[8];
    const float* p_rate  = (const float*)d_in[9];

    const int B = in_sizes[0] / 5;
    int blocks = (B + RPB - 1) / RPB;
    if (blocks < 1) blocks = 1;

    precompute_kernel<<<2, 256>>>(table, w, p_rho, p_beta, p_tau, p_gamma);
    rank_rt_kernel<<<blocks, TPB>>>(stim, p_upper, p_mid, p_rate,
                                    (float*)d_out, B);
}

// round 10
// speedup vs baseline: 1.6906x; 1.1057x over previous
#include <cuda_runtime.h>
#include <cstdint>

#define NS 21              // N_STIM + 1
#define PAIRS 441          // NS*NS
#define PAIRS_PAD 442      // pad so table bytes (442*8=3536) is a multiple of 16
#define TAB_BYTES (PAIRS_PAD * 8)
#define TPB 256
#define RPT 4              // rows per thread
#define RPB (TPB * RPT)    // 1024 rows per block

__device__ alignas(16) float2 g_tab[PAIRS_PAD];   // {s, s*ln(s)} per (q,r) pair

// ---------------- kernel 1: compute the 441-entry pair table once ----------------
__global__ void precompute_kernel(const float* __restrict__ table,
                                  const float* __restrict__ w,
                                  const float* __restrict__ p_rho,
                                  const float* __restrict__ p_beta,
                                  const float* __restrict__ p_tau,
                                  const float* __restrict__ p_gamma)
{
    const int e = blockIdx.x * blockDim.x + threadIdx.x;
    if (e >= PAIRS) return;
    const float rho   = *p_rho;
    const float beta  = *p_beta;
    const float tau   = *p_tau;
    const float gamma = *p_gamma;
    const float w0 = w[0], w1 = w[1], w2 = w[2];

    const int q = e / NS, r = e % NS;
    const float dx = fabsf(table[q * 3 + 0] - table[r * 3 + 0]);
    const float dy = fabsf(table[q * 3 + 1] - table[r * 3 + 1]);
    const float dz = fabsf(table[q * 3 + 2] - table[r * 3 + 2]);

    float s;
    if (rho == 2.0f && tau == 1.0f) {
        // fast path for the actual parameterization: no powf
        const float acc = w0 * dx * dx + w1 * dy * dy + w2 * dz * dz;
        const float d   = sqrtf(acc);
        s = __expf(-beta * d) + gamma;
    } else {
        const float inv_rho = 1.0f / rho;
        const float acc = w0 * powf(dx, rho) + w1 * powf(dy, rho) + w2 * powf(dz, rho);
        const float d   = powf(acc, inv_rho);
        s = expf(-beta * powf(d, tau)) + gamma;
    }
    g_tab[e] = make_float2(s, s * __logf(s));
}

// ---------------- PTX helpers ----------------
__device__ __forceinline__ uint32_t smem_u32(const void* p) {
    uint32_t a;
    asm("{ .reg .u64 t; cvta.to.shared.u64 t, %1; cvt.u32.u64 %0, t; }"
        : "=r"(a) : "l"(p));
    return a;
}

// ---------------- kernel 2: main lookup kernel, TMA-bulk staged ----------------
__global__ void __launch_bounds__(TPB)
rank_rt_kernel(const int*   __restrict__ stim,    // [B,5]
               const float* __restrict__ p_upper,
               const float* __restrict__ p_mid,
               const float* __restrict__ p_rate,
               float* __restrict__ out,           // [B*4 rank | B rt]
               int B)
{
    __shared__ alignas(16) float2   sTab[PAIRS_PAD];
    __shared__ alignas(16) int      sIdx[RPB * 5];
    __shared__ alignas(8)  uint64_t mbar;

    const int row0 = blockIdx.x * RPB;
    const int rows = min(RPB, B - row0);
    const int bulkRows  = rows & ~3;              // bulk size must be 16B multiple
    const uint32_t bulkBytes = (uint32_t)bulkRows * 20u;

    const uint32_t mbarA = smem_u32(&mbar);

    if (threadIdx.x == 0)
        asm volatile("mbarrier.init.shared.b64 [%0], 1;" :: "r"(mbarA) : "memory");
    __syncthreads();   // init visible to all threads before they wait

    if (threadIdx.x == 0) {
        const uint32_t tx = TAB_BYTES + bulkBytes;
        asm volatile("mbarrier.arrive.expect_tx.shared.b64 _, [%0], %1;"
                     :: "r"(mbarA), "r"(tx) : "memory");
        // table copy: 3536 B, global -> shared (async proxy, off the L1TEX path)
        asm volatile("cp.async.bulk.shared::cta.global.mbarrier::complete_tx::bytes "
                     "[%0], [%1], %2, [%3];"
                     :: "r"(smem_u32(sTab)), "l"((const void*)g_tab),
                        "r"((uint32_t)TAB_BYTES), "r"(mbarA) : "memory");
        // index block copy: bulkRows * 20 B
        if (bulkBytes > 0) {
            asm volatile("cp.async.bulk.shared::cta.global.mbarrier::complete_tx::bytes "
                         "[%0], [%1], %2, [%3];"
                         :: "r"(smem_u32(sIdx)), "l"((const void*)(stim + (size_t)row0 * 5)),
                            "r"(bulkBytes), "r"(mbarA) : "memory");
        }
    }

    // scalar fill for tail rows not covered by the bulk copy (<=15 ints, last block only)
    const int remInts = rows * 5 - bulkRows * 5;
    for (int k = threadIdx.x; k < remInts; k += TPB)
        sIdx[bulkRows * 5 + k] = stim[(size_t)row0 * 5 + bulkRows * 5 + k];

    // wait for bulk copies (acquire orders subsequent LDS against TMA writes)
    {
        uint32_t done;
        asm volatile("{\n\t.reg .pred p;\n\t"
                     "mbarrier.try_wait.parity.acquire.cta.shared::cta.b64 p, [%1], 0;\n\t"
                     "selp.b32 %0, 1, 0, p;\n\t}"
                     : "=r"(done) : "r"(mbarA) : "memory");
        if (!done) {
            asm volatile("{\n\t.reg .pred P1;\n\t"
                         "W_%=:\n\t"
                         "mbarrier.try_wait.parity.acquire.cta.shared::cta.b64 P1, [%0], 0, 0x989680;\n\t"
                         "@P1 bra.uni D_%=;\n\t"
                         "bra.uni W_%=;\n\t"
                         "D_%=:\n\t}"
                         :: "r"(mbarA) : "memory");
        }
    }
    if (remInts > 0) __syncthreads();   // order scalar tail fills (last block only)

    const float upper = *p_upper;
    const float mid   = *p_mid;
    const float rate  = *p_rate;
    float* __restrict__ rt_out = out + (size_t)B * 4;

    #pragma unroll
    for (int h = 0; h < RPT; h++) {
        const int lrow = threadIdx.x + h * TPB;
        const int row  = row0 + lrow;
        if (row >= B) break;

        const int* rp = &sIdx[lrow * 5];           // stride-5: bank-conflict-free
        const int qb = rp[0] * NS;
        const float2 e0 = sTab[qb + rp[1]];
        const float2 e1 = sTab[qb + rp[2]];
        const float2 e2 = sTab[qb + rp[3]];
        const float2 e3 = sTab[qb + rp[4]];

        const float S  = (e0.x + e1.x) + (e2.x + e3.x);
        const float SL = (e0.y + e1.y) + (e2.y + e3.y);
        const float inv = __fdividef(1.0f, S);

        reinterpret_cast<float4*>(out)[row] =
            make_float4(e0.x * inv, e1.x * inv, e2.x * inv, e3.x * inv);

        const float H = __logf(S) - SL * inv;      // entropy
        rt_out[row] = upper * __fdividef(1.0f, 1.0f + __expf(-rate * (H - mid)));
    }
}

extern "C" void kernel_launch(void* const* d_in, const int* in_sizes, int n_in,
                              void* d_out, int out_size)
{
    const int*   stim    = (const int*)  d_in[0];
    const float* table   = (const float*)d_in[1];
    const float* w       = (const float*)d_in[2];
    const float* p_rho   = (const float*)d_in[3];
    const float* p_beta  = (const float*)d_in[4];
    const float* p_tau   = (const float*)d_in[5];
    const float* p_gamma = (const float*)d_in[6];
    const float* p_upper = (const float*)d_in[7];
    const float* p_mid   = (const float*)d_in[8];
    const float* p_rate  = (const float*)d_in[9];

    const int B = in_sizes[0] / 5;
    int blocks = (B + RPB - 1) / RPB;
    if (blocks < 1) blocks = 1;

    precompute_kernel<<<2, 256>>>(table, w, p_rho, p_beta, p_tau, p_gamma);
    rank_rt_kernel<<<blocks, TPB>>>(stim, p_upper, p_mid, p_rate,
                                    (float*)d_out, B);
}

// round 11
// speedup vs baseline: 1.7466x; 1.0331x over previous
#include <cuda_runtime.h>
#include <cstdint>

#define NS 21              // N_STIM + 1
#define PAIRS 441          // NS*NS
#define PAIRS_PAD 442      // pad so table bytes (442*8=3536) is a multiple of 16
#define TAB_BYTES (PAIRS_PAD * 8)
#define TPB 256
#define RPT 4              // rows per thread
#define RPB (TPB * RPT)    // 1024 rows per block

__device__ alignas(16) float2 g_tab[PAIRS_PAD];   // {s, s*ln(s)} per (q,r) pair

// ---------------- kernel 1: compute the 441-entry pair table once ----------------
__global__ void precompute_kernel(const float* __restrict__ table,
                                  const float* __restrict__ w,
                                  const float* __restrict__ p_rho,
                                  const float* __restrict__ p_beta,
                                  const float* __restrict__ p_tau,
                                  const float* __restrict__ p_gamma)
{
    const int e = blockIdx.x * blockDim.x + threadIdx.x;
    if (e >= PAIRS) return;
    const float rho   = *p_rho;
    const float beta  = *p_beta;
    const float tau   = *p_tau;
    const float gamma = *p_gamma;
    const float w0 = w[0], w1 = w[1], w2 = w[2];

    const int q = e / NS, r = e % NS;
    const float dx = fabsf(table[q * 3 + 0] - table[r * 3 + 0]);
    const float dy = fabsf(table[q * 3 + 1] - table[r * 3 + 1]);
    const float dz = fabsf(table[q * 3 + 2] - table[r * 3 + 2]);

    float s;
    if (rho == 2.0f && tau == 1.0f) {
        // fast path for the actual parameterization: no powf
        const float acc = w0 * dx * dx + w1 * dy * dy + w2 * dz * dz;
        const float d   = sqrtf(acc);
        s = __expf(-beta * d) + gamma;
    } else {
        const float inv_rho = 1.0f / rho;
        const float acc = w0 * powf(dx, rho) + w1 * powf(dy, rho) + w2 * powf(dz, rho);
        const float d   = powf(acc, inv_rho);
        s = expf(-beta * powf(d, tau)) + gamma;
    }
    g_tab[e] = make_float2(s, s * __logf(s));
}

// ---------------- PTX helpers ----------------
__device__ __forceinline__ uint32_t smem_u32(const void* p) {
    uint32_t a;
    asm("{ .reg .u64 t; cvta.to.shared.u64 t, %1; cvt.u32.u64 %0, t; }"
        : "=r"(a) : "l"(p));
    return a;
}

// ---------------- kernel 2: main lookup kernel, TMA staged + 4-row batched ----------------
__global__ void __launch_bounds__(TPB, 3)
rank_rt_kernel(const int*   __restrict__ stim,    // [B,5]
               const float* __restrict__ p_upper,
               const float* __restrict__ p_mid,
               const float* __restrict__ p_rate,
               float* __restrict__ out,           // [B*4 rank | B rt]
               int B)
{
    __shared__ alignas(16) float2   sTab[PAIRS_PAD];
    __shared__ alignas(16) int      sIdx[RPB * 5];
    __shared__ alignas(8)  uint64_t mbar;

    const int row0 = blockIdx.x * RPB;
    const int rows = min(RPB, B - row0);
    const int bulkRows  = rows & ~3;              // bulk size must be 16B multiple
    const uint32_t bulkBytes = (uint32_t)bulkRows * 20u;

    const uint32_t mbarA = smem_u32(&mbar);

    if (threadIdx.x == 0)
        asm volatile("mbarrier.init.shared.b64 [%0], 1;" :: "r"(mbarA) : "memory");
    __syncthreads();   // init visible to all threads before they wait

    if (threadIdx.x == 0) {
        const uint32_t tx = TAB_BYTES + bulkBytes;
        asm volatile("mbarrier.arrive.expect_tx.shared.b64 _, [%0], %1;"
                     :: "r"(mbarA), "r"(tx) : "memory");
        // table copy: 3536 B, global -> shared (async proxy, off the L1TEX path)
        asm volatile("cp.async.bulk.shared::cta.global.mbarrier::complete_tx::bytes "
                     "[%0], [%1], %2, [%3];"
                     :: "r"(smem_u32(sTab)), "l"((const void*)g_tab),
                        "r"((uint32_t)TAB_BYTES), "r"(mbarA) : "memory");
        // index block copy: bulkRows * 20 B
        if (bulkBytes > 0) {
            asm volatile("cp.async.bulk.shared::cta.global.mbarrier::complete_tx::bytes "
                         "[%0], [%1], %2, [%3];"
                         :: "r"(smem_u32(sIdx)), "l"((const void*)(stim + (size_t)row0 * 5)),
                            "r"(bulkBytes), "r"(mbarA) : "memory");
        }
    }

    // tail block only: scalar-fill remaining valid ints, zero the rest so
    // unguarded batched lookups stay in-bounds (index 0 is always safe)
    if (rows < RPB) {
        for (int k = bulkRows * 5 + threadIdx.x; k < RPB * 5; k += TPB)
            sIdx[k] = (k < rows * 5) ? stim[(size_t)row0 * 5 + k] : 0;
    }

    // wait for bulk copies (acquire orders subsequent LDS against TMA writes)
    {
        uint32_t done;
        asm volatile("{\n\t.reg .pred p;\n\t"
                     "mbarrier.try_wait.parity.acquire.cta.shared::cta.b64 p, [%1], 0;\n\t"
                     "selp.b32 %0, 1, 0, p;\n\t}"
                     : "=r"(done) : "r"(mbarA) : "memory");
        if (!done) {
            asm volatile("{\n\t.reg .pred P1;\n\t"
                         "W_%=:\n\t"
                         "mbarrier.try_wait.parity.acquire.cta.shared::cta.b64 P1, [%0], 0, 0x989680;\n\t"
                         "@P1 bra.uni D_%=;\n\t"
                         "bra.uni W_%=;\n\t"
                         "D_%=:\n\t}"
                         :: "r"(mbarA) : "memory");
        }
    }
    if (rows < RPB) __syncthreads();   // order scalar tail fills (uniform per block)

    const float upper = *p_upper;
    const float mid   = *p_mid;
    const float rate  = *p_rate;
    float* __restrict__ rt_out = out + (size_t)B * 4;

    // ---- explicit 4-row batch: all index loads, then all lookups, then math ----
    int idx[RPT][5];
    #pragma unroll
    for (int h = 0; h < RPT; h++) {
        const int lrow = threadIdx.x + h * TPB;
        #pragma unroll
        for (int c = 0; c < 5; c++)
            idx[h][c] = sIdx[lrow * 5 + c];        // stride-5: conflict-free
    }

    float2 e[RPT][4];
    #pragma unroll
    for (int h = 0; h < RPT; h++) {
        const int qb = idx[h][0] * NS;
        #pragma unroll
        for (int c = 0; c < 4; c++)
            e[h][c] = sTab[qb + idx[h][c + 1]];
    }

    #pragma unroll
    for (int h = 0; h < RPT; h++) {
        const int row = row0 + threadIdx.x + h * TPB;
        if (row < B) {
            const float S  = (e[h][0].x + e[h][1].x) + (e[h][2].x + e[h][3].x);
            const float SL = (e[h][0].y + e[h][1].y) + (e[h][2].y + e[h][3].y);
            const float inv = __fdividef(1.0f, S);

            reinterpret_cast<float4*>(out)[row] =
                make_float4(e[h][0].x * inv, e[h][1].x * inv,
                            e[h][2].x * inv, e[h][3].x * inv);

            const float H = __logf(S) - SL * inv;  // entropy
            rt_out[row] = upper * __fdividef(1.0f, 1.0f + __expf(-rate * (H - mid)));
        }
    }
}

extern "C" void kernel_launch(void* const* d_in, const int* in_sizes, int n_in,
                              void* d_out, int out_size)
{
    const int*   stim    = (const int*)  d_in[0];
    const float* table   = (const float*)d_in[1];
    const float* w       = (const float*)d_in[2];
    const float* p_rho   = (const float*)d_in[3];
    const float* p_beta  = (const float*)d_in[4];
    const float* p_tau   = (const float*)d_in[5];
    const float* p_gamma = (const float*)d_in[6];
    const float* p_upper = (const float*)d_in[7];
    const float* p_mid   = (const float*)d_in[8];
    const float* p_rate  = (const float*)d_in[9];

    const int B = in_sizes[0] / 5;
    int blocks = (B + RPB - 1) / RPB;
    if (blocks < 1) blocks = 1;

    precompute_kernel<<<2, 256>>>(table, w, p_rho, p_beta, p_tau, p_gamma);
    rank_rt_kernel<<<blocks, TPB>>>(stim, p_upper, p_mid, p_rate,
                                    (float*)d_out, B);
}